// round 13
// baseline (speedup 1.0000x reference)
#include <cuda_runtime.h>
#include <cuda_bf16.h>
#include <cstdint>

#define BB 8
#define NN 2048
#define DD 128
#define NEG 0.2f
#define BN (BB*NN)

#define KCHUNK 64
#define NCHUNKS (NN/KCHUNK)   // 32
#define TILE_N 64

// ---------------- scratch (device globals) ----------------
__device__ __align__(16) unsigned short g_hT1[(size_t)BB*DD*NN];  // bf16 hi part of h^T [b][d][m]
__device__ __align__(16) unsigned short g_hT2[(size_t)BB*DD*NN];  // bf16 residual part
__device__ __align__(16) float  g_eA[BN];              // exp(s_i)
__device__ __align__(16) float  g_eC[BN];              // exp(0.2 s_i)
__device__ __align__(16) float2 g_e12[BN];             // {exp(s_j), exp(0.2 s_j)}
__device__ __align__(16) unsigned g_adj[NN*(NN/32)];   // packed adjacency bitmask

// ---------------- helpers ----------------
__device__ __forceinline__ uint32_t smem_to_u32(const void* p) {
    uint32_t a;
    asm("{ .reg .u64 t; cvta.to.shared.u64 t, %1; cvt.u32.u64 %0, t; }"
        : "=r"(a) : "l"(p));
    return a;
}
#define SW128(off) ((off) ^ (((off) >> 3) & 0x70))

__device__ __forceinline__ void ldsm4(uint32_t* r, uint32_t addr) {
    asm volatile("ldmatrix.sync.aligned.m8n8.x4.shared.b16 {%0,%1,%2,%3}, [%4];"
        : "=r"(r[0]), "=r"(r[1]), "=r"(r[2]), "=r"(r[3]) : "r"(addr));
}
__device__ __forceinline__ void mma_bf16(float* c, const uint32_t* a,
                                         uint32_t b0, uint32_t b1) {
    asm volatile(
        "mma.sync.aligned.m16n8k16.row.col.f32.bf16.bf16.f32 "
        "{%0,%1,%2,%3}, {%4,%5,%6,%7}, {%8,%9}, {%0,%1,%2,%3};"
        : "+f"(c[0]), "+f"(c[1]), "+f"(c[2]), "+f"(c[3])
        : "r"(a[0]), "r"(a[1]), "r"(a[2]), "r"(a[3]), "r"(b0), "r"(b1));
}

// bf16 2-term split: p1 = bf16x2(a0,a1) (lo=a0), p2 = bf16x2 of residuals
__device__ __forceinline__ void bsplit(float a0, float a1, unsigned& p1, unsigned& p2) {
    asm("cvt.rn.bf16x2.f32 %0, %2, %1;" : "=r"(p1) : "f"(a0), "f"(a1));
    float b0 = __uint_as_float(p1 << 16);
    float b1 = __uint_as_float(p1 & 0xffff0000u);
    float r0 = a0 - b0, r1 = a1 - b1;
    asm("cvt.rn.bf16x2.f32 %0, %2, %1;" : "=r"(p2) : "f"(r0), "f"(r1));
}

// ---------------- pack adjacency into bitmask (int4 + nibble shuffle) ----------------
// grid 1024, block 256: warp-iter consumes 128 ints -> 4 words; 4 iters/warp
__global__ void k_pack(const int* __restrict__ adj) {
    int tid = threadIdx.x;
    int lane = tid & 31, wid = tid >> 5;
    int warp_g = blockIdx.x * 8 + wid;
    const int4* src = (const int4*)adj;
    int word0 = warp_g * 16;                  // first output word of this warp
#pragma unroll
    for (int t = 0; t < 4; t++) {
        int w4 = word0 + t*4;                 // 4 words this iter
        int4 v = src[(size_t)w4*8 + lane];    // 128 ints across warp
        unsigned nib = ((v.x>0)?1u:0u) | ((v.y>0)?2u:0u)
                     | ((v.z>0)?4u:0u) | ((v.w>0)?8u:0u);
        unsigned val = nib << ((lane & 7) * 4);
        val |= __shfl_xor_sync(0xffffffffu, val, 1);
        val |= __shfl_xor_sync(0xffffffffu, val, 2);
        val |= __shfl_xor_sync(0xffffffffu, val, 4);
        if ((lane & 7) == 0) g_adj[w4 + (lane >> 3)] = val;
    }
}

// ---------------- h = x@W -> hT bf16 splits + s/exp arrays ----------------
__global__ void k_h(const float* __restrict__ x, const float* __restrict__ W,
                    const float* __restrict__ a_vec) {
    __shared__ float xs[32*128];
    int tid = threadIdx.x;
    int row0 = blockIdx.x * 32;
    for (int i = tid; i < 32*128; i += 128) xs[i] = x[(size_t)row0*128 + i];
    __syncthreads();
    float acc[32];
#pragma unroll
    for (int r = 0; r < 32; r++) acc[r] = 0.f;
#pragma unroll 2
    for (int k = 0; k < 128; k++) {
        float wv = W[k*128 + tid];
#pragma unroll
        for (int r = 0; r < 32; r++) acc[r] += xs[r*128 + k] * wv;
    }
    int b = row0 >> 11;
    int mbase = row0 & 2047;
    {
        unsigned u1[16], u2[16];
#pragma unroll
        for (int k = 0; k < 16; k++) bsplit(acc[2*k], acc[2*k+1], u1[k], u2[k]);
        size_t base = ((size_t)(b*DD + tid) * NN + mbase) >> 1;
        uint4* d1 = (uint4*)((unsigned*)g_hT1 + base);
        uint4* d2 = (uint4*)((unsigned*)g_hT2 + base);
#pragma unroll
        for (int k = 0; k < 4; k++) {
            d1[k] = *(uint4*)(u1 + 4*k);
            d2[k] = *(uint4*)(u2 + 4*k);
        }
    }
    __syncthreads();
#pragma unroll
    for (int r = 0; r < 32; r++) xs[r*128 + tid] = acc[r];
    __syncthreads();
    int warp = tid >> 5, lane = tid & 31;
    float4 a14 = *(const float4*)(a_vec + lane*4);
    float4 a24 = *(const float4*)(a_vec + 128 + lane*4);
#pragma unroll
    for (int k = 0; k < 8; k++) {
        int r = warp*8 + k;
        float4 hv = *(const float4*)(xs + r*128 + lane*4);
        float s1 = hv.x*a14.x + hv.y*a14.y + hv.z*a14.z + hv.w*a14.w;
        float s2 = hv.x*a24.x + hv.y*a24.y + hv.z*a24.z + hv.w*a24.w;
#pragma unroll
        for (int o = 16; o; o >>= 1) {
            s1 += __shfl_xor_sync(0xffffffffu, s1, o);
            s2 += __shfl_xor_sync(0xffffffffu, s2, o);
        }
        if (lane == 0) {
            int gr = row0 + r;
            g_eA[gr] = __expf(s1);
            g_eC[gr] = __expf(NEG * s1);
            g_e12[gr] = make_float2(__expf(s2), __expf(NEG * s2));
        }
    }
}

// ---------------- smem layout (~83 KB → 2 CTAs/SM) — machine-checked ----------------
#define SM_A1   0u          // 8 KB (64 x 128B)
#define SM_A2   8192u       // 8 KB
#define SM_B1   16384u      // 16 KB (128 x 128B)
#define SM_B2   32768u      // 16 KB
#define SM_E12  49152u      // 16 KB
#define SM_ADJ  65536u      // 16 KB (64 rows x 64 words)
#define SM_ROW  81920u      // 3 x 64 floats
#define SM_TOTAL (81920u + 768u)

static_assert(SM_A2  >= SM_A1  + 64u*128u,   "A1/A2 overlap");
static_assert(SM_B1  >= SM_A2  + 64u*128u,   "A2/B1 overlap");
static_assert(SM_B2  >= SM_B1  + 128u*128u,  "B1/B2 overlap");
static_assert(SM_E12 >= SM_B2  + 128u*128u,  "B2/E12 overlap");
static_assert(SM_ADJ >= SM_E12 + 16384u,     "E12/ADJ overlap");
static_assert(SM_ROW >= SM_ADJ + 64u*64u*4u, "ADJ/ROW overlap");
static_assert(SM_TOTAL >= SM_ROW + 3u*64u*4u, "ROW overflow");
static_assert(SM_TOTAL <= 227u*1024u, "smem over limit");
// k-split reduction buffers: 4 x 16 KB regions reuse A1..B2 (64 KB); padded rows 136B
static_assert(64u*136u <= 16384u, "red region overflow");

// ---------------- fused softmax + alpha + HMMA alpha@h (k-split warps) ----------------
// grid (32, 8), block 256: 8 warps = 4 d-groups x 2 k-groups, warp tile 64n x 32d x 32k
__global__ void __launch_bounds__(256, 2) k_main(float* __restrict__ out,
                                                 float* __restrict__ alpha) {
    extern __shared__ __align__(1024) char smem[];
    uint32_t sb = smem_to_u32(smem);
    int tid = threadIdx.x, wid = tid >> 5, lane = tid & 31;
    int b = blockIdx.y, n0 = blockIdx.x * TILE_N;

    float*    e12f = (float*)(smem + SM_E12);
    unsigned* adjs = (unsigned*)(smem + SM_ADJ);
    float* AiSh = (float*)(smem + SM_ROW);
    float* CiSh = AiSh + TILE_N;
    float* RvSh = CiSh + TILE_N;

    // stage e12 (16KB) and adj bitmask (16KB)
    {
        const uint4* s = (const uint4*)(g_e12 + b*NN);
        uint4* d = (uint4*)e12f;
#pragma unroll
        for (int k = 0; k < 4; k++) d[tid + k*256] = s[tid + k*256];
    }
    {
        const uint4* s = (const uint4*)(g_adj + (size_t)n0*64);
        uint4* d = (uint4*)adjs;
#pragma unroll
        for (int k = 0; k < 4; k++) d[tid + k*256] = s[tid + k*256];
    }
    if (tid < TILE_N) {
        AiSh[tid] = g_eA[b*NN + n0 + tid];
        CiSh[tid] = g_eC[b*NN + n0 + tid];
    }
    __syncthreads();

    // ---- pass B: row softmax denominators (8 rows per warp) ----
#pragma unroll 1
    for (int k = 0; k < 8; k++) {
        int r = wid*8 + k;
        float Ai = AiSh[r], Ci = CiSh[r];
        const unsigned* arow = adjs + r*64;
        float sum = 0.f;
#pragma unroll 4
        for (int i2 = 0; i2 < 32; i2++) {
            float4 ev = *(const float4*)(e12f + i2*128 + lane*4);
            unsigned bits = arow[i2*2 + (lane >> 4)];
            unsigned bp = (lane & 15) * 2;
            float nu0 = fmaxf(Ai*ev.x, Ci*ev.y);
            float nu1 = fmaxf(Ai*ev.z, Ci*ev.w);
            sum += ((bits >> bp) & 1u) ? nu0 : 0.f;
            sum += ((bits >> (bp+1)) & 1u) ? nu1 : 0.f;
        }
#pragma unroll
        for (int o = 16; o; o >>= 1) sum += __shfl_xor_sync(0xffffffffu, sum, o);
        if (lane == 0) RvSh[r] = 1.f / sum;
    }
    __syncthreads();

    // coalesced alpha mapping: per warp 8 rows; iter i covers rows wid*8+2i+half
    int q = lane & 15, half = lane >> 4;

    // B staging via reg prefetch: 4 rows/thread/split (rows brow+32i)
    int brow = tid >> 3, bq = tid & 7;
    size_t gbase = ((size_t)(b*128 + brow))*256 + bq;     // uint4 units
    unsigned bsw = SW128((unsigned)(brow*128 + bq*16));
    const uint4* gB1 = (const uint4*)g_hT1;
    const uint4* gB2 = (const uint4*)g_hT2;

    // k-split warp GEMM tiling: warp -> all 64 n, d-quarter 32, k-half 32
    int dg4 = wid & 3, kg = wid >> 2;
    int d0w = dg4 * 32;
    int arow_l = lane & 15;
    unsigned acol_l = (lane >> 4) * 16;
    int brow_l = (lane & 7) + ((lane >> 4) << 3);
    unsigned bcol_l = ((lane >> 3) & 1) * 16;
    unsigned a_xor = (unsigned)((arow_l & 7) << 4);
    unsigned b_xor = (unsigned)((brow_l & 7) << 4);
    uint32_t a_row_base = sb + SM_A1 + (unsigned)(arow_l * 128);
    uint32_t b_row_base = sb + SM_B1 + (unsigned)((d0w + brow_l) * 128);
    int kg2 = kg * 2;

    float acc[4][4][4];   // [ngroup16][d8tile][reg]
#pragma unroll
    for (int i = 0; i < 4; i++)
#pragma unroll
        for (int j = 0; j < 4; j++)
#pragma unroll
            for (int k = 0; k < 4; k++) acc[i][j][k] = 0.f;

    // prefetch chunk 0
    uint4 v1[4], v2[4];
#pragma unroll
    for (int i = 0; i < 4; i++) {
        v1[i] = gB1[gbase + (size_t)i*8192];
        v2[i] = gB2[gbase + (size_t)i*8192];
    }

    for (int c = 0; c < NCHUNKS; c++) {
        int m0 = c * KCHUNK;
        // STS B tiles
#pragma unroll
        for (int i = 0; i < 4; i++) {
            *(uint4*)(smem + SM_B1 + bsw + i*4096) = v1[i];
            *(uint4*)(smem + SM_B2 + bsw + i*4096) = v2[i];
        }
        // alpha: COALESCED — iter i: rows wid*8+2i+half, m = m0 + q*4
#pragma unroll
        for (int i = 0; i < 4; i++) {
            int rr = wid*8 + i*2 + half;
            float Ai = AiSh[rr], Ci = CiSh[rr], Rv = RvSh[rr];
            int mloc = q*4;
            int m = m0 + mloc;
            float4 e01 = *(const float4*)(e12f + 2*m);
            float4 e23 = *(const float4*)(e12f + 2*m + 4);
            float n0v = fmaxf(Ai*e01.x, Ci*e01.y);
            float n1v = fmaxf(Ai*e01.z, Ci*e01.w);
            float n2v = fmaxf(Ai*e23.x, Ci*e23.y);
            float n3v = fmaxf(Ai*e23.z, Ci*e23.w);
            unsigned bits = adjs[rr*64 + c*2 + (q >> 3)];
            unsigned bp = (unsigned)((q & 7) * 4);
            float a0 = ((bits >> (bp+0)) & 1u) ? n0v*Rv : 0.f;
            float a1 = ((bits >> (bp+1)) & 1u) ? n1v*Rv : 0.f;
            float a2 = ((bits >> (bp+2)) & 1u) ? n2v*Rv : 0.f;
            float a3 = ((bits >> (bp+3)) & 1u) ? n3v*Rv : 0.f;
            __stwt((float4*)(alpha + ((size_t)(b*NN + n0 + rr))*NN + m),
                   make_float4(a0, a1, a2, a3));
            unsigned p1a, p2a, p1b, p2b;
            bsplit(a0, a1, p1a, p2a);
            bsplit(a2, a3, p1b, p2b);
            unsigned so = SW128((unsigned)(rr*128 + mloc*2));
            *(uint2*)(smem + SM_A1 + so) = make_uint2(p1a, p1b);
            *(uint2*)(smem + SM_A2 + so) = make_uint2(p2a, p2b);
        }
        __syncthreads();

        // prefetch next chunk (hidden under the MMA phase)
        if (c + 1 < NCHUNKS) {
            size_t mo = (size_t)((m0 + KCHUNK) >> 3);
#pragma unroll
            for (int i = 0; i < 4; i++) {
                v1[i] = gB1[gbase + (size_t)i*8192 + mo];
                v2[i] = gB2[gbase + (size_t)i*8192 + mo];
            }
        }

        // MMA: this warp's 2 k-steps, term-major, A regs reused across terms
#pragma unroll
        for (int j = 0; j < 2; j++) {
            int ks = kg2 + j;
            unsigned acol = (acol_l + ks*32) ^ a_xor;
            unsigned bcol = (bcol_l + ks*32) ^ b_xor;
            uint32_t af[4][4], b1f[2][4], b2f[2][4];
#pragma unroll
            for (int ng = 0; ng < 4; ng++) ldsm4(af[ng], a_row_base + ng*2048 + acol);
#pragma unroll
            for (int dg = 0; dg < 2; dg++) {
                ldsm4(b1f[dg], b_row_base + dg*2048 + bcol);
                ldsm4(b2f[dg], b_row_base + dg*2048 + bcol + 16384u);
            }
            // term 1: a1*h1
#pragma unroll
            for (int ng = 0; ng < 4; ng++)
#pragma unroll
                for (int dg = 0; dg < 2; dg++) {
                    mma_bf16(acc[ng][dg*2+0], af[ng], b1f[dg][0], b1f[dg][1]);
                    mma_bf16(acc[ng][dg*2+1], af[ng], b1f[dg][2], b1f[dg][3]);
                }
            // term 2: a1*h2
#pragma unroll
            for (int ng = 0; ng < 4; ng++)
#pragma unroll
                for (int dg = 0; dg < 2; dg++) {
                    mma_bf16(acc[ng][dg*2+0], af[ng], b2f[dg][0], b2f[dg][1]);
                    mma_bf16(acc[ng][dg*2+1], af[ng], b2f[dg][2], b2f[dg][3]);
                }
            // reload A residual, term 3: a2*h1
#pragma unroll
            for (int ng = 0; ng < 4; ng++) ldsm4(af[ng], a_row_base + ng*2048 + acol + 8192u);
#pragma unroll
            for (int ng = 0; ng < 4; ng++)
#pragma unroll
                for (int dg = 0; dg < 2; dg++) {
                    mma_bf16(acc[ng][dg*2+0], af[ng], b1f[dg][0], b1f[dg][1]);
                    mma_bf16(acc[ng][dg*2+1], af[ng], b1f[dg][2], b1f[dg][3]);
                }
        }
        __syncthreads();
    }

    // ---- cross-k reduction (kg=1 partials -> kg=0) then epilogue ----
    // red region per dg4: 16 KB at SM_A1 + dg4*16384, padded row stride 136B
    char* red = smem + SM_A1 + (unsigned)(dg4 * 16384);
    if (kg == 1) {
#pragma unroll
        for (int ng = 0; ng < 4; ng++)
#pragma unroll
            for (int dt = 0; dt < 4; dt++) {
                int r = ng*16 + (lane >> 2);
                int cc = dt*8 + (lane & 3)*2;
                *(float2*)(red + r*136 + cc*4) =
                    make_float2(acc[ng][dt][0], acc[ng][dt][1]);
                *(float2*)(red + (r+8)*136 + cc*4) =
                    make_float2(acc[ng][dt][2], acc[ng][dt][3]);
            }
    }
    __syncthreads();
    if (kg == 0) {
#pragma unroll
        for (int ng = 0; ng < 4; ng++)
#pragma unroll
            for (int dt = 0; dt < 4; dt++) {
                int r = ng*16 + (lane >> 2);
                int cc = dt*8 + (lane & 3)*2;
                float2 p0 = *(const float2*)(red + r*136 + cc*4);
                float2 p1 = *(const float2*)(red + (r+8)*136 + cc*4);
                float* op = out + ((size_t)(b*NN + n0 + r))*DD + d0w + cc;
                *(float2*)op = make_float2(acc[ng][dt][0] + p0.x,
                                           acc[ng][dt][1] + p0.y);
                *(float2*)(op + 8*DD) = make_float2(acc[ng][dt][2] + p1.x,
                                                    acc[ng][dt][3] + p1.y);
            }
    }
}

// ---------------- launch ----------------
extern "C" void kernel_launch(void* const* d_in, const int* in_sizes, int n_in,
                              void* d_out, int out_size) {
    const float* x    = (const float*)d_in[0];
    const int*   adj  = (const int*)  d_in[1];
    const float* W    = (const float*)d_in[2];
    const float* avec = (const float*)d_in[3];
    float* out   = (float*)d_out;
    float* alpha = out + (size_t)BN*DD;

    cudaFuncSetAttribute(k_main, cudaFuncAttributeMaxDynamicSharedMemorySize,
                         SM_TOTAL);

    k_pack<<<1024, 256>>>(adj);
    k_h<<<BN/32, 128>>>(x, W, avec);
    dim3 grid(NN/TILE_N, BB);
    k_main<<<grid, 256, SM_TOTAL>>>(out, alpha);
}

// round 14
// speedup vs baseline: 1.1505x; 1.1505x over previous
#include <cuda_runtime.h>
#include <cuda_bf16.h>
#include <cstdint>

#define BB 8
#define NN 2048
#define DD 128
#define NEG 0.2f
#define BN (BB*NN)

#define KCHUNK 64
#define NCHUNKS (NN/KCHUNK)   // 32
#define TILE_N 128

// ---------------- scratch (device globals) ----------------
__device__ __align__(16) unsigned short g_hT1[(size_t)BB*DD*NN];  // bf16 hi part of h^T [b][d][m]
__device__ __align__(16) unsigned short g_hT2[(size_t)BB*DD*NN];  // bf16 residual part
__device__ __align__(16) float  g_eA[BN];              // exp(s_i)
__device__ __align__(16) float  g_eC[BN];              // exp(0.2 s_i)
__device__ __align__(16) float2 g_e12[BN];             // {exp(s_j), exp(0.2 s_j)}
__device__ __align__(16) unsigned g_adj[NN*(NN/32)];   // packed adjacency bitmask

// ---------------- helpers ----------------
__device__ __forceinline__ uint32_t smem_to_u32(const void* p) {
    uint32_t a;
    asm("{ .reg .u64 t; cvta.to.shared.u64 t, %1; cvt.u32.u64 %0, t; }"
        : "=r"(a) : "l"(p));
    return a;
}
#define SW128(off) ((off) ^ (((off) >> 3) & 0x70))

__device__ __forceinline__ void ldsm4(uint32_t* r, uint32_t addr) {
    asm volatile("ldmatrix.sync.aligned.m8n8.x4.shared.b16 {%0,%1,%2,%3}, [%4];"
        : "=r"(r[0]), "=r"(r[1]), "=r"(r[2]), "=r"(r[3]) : "r"(addr));
}
__device__ __forceinline__ void mma_bf16(float* c, const uint32_t* a,
                                         uint32_t b0, uint32_t b1) {
    asm volatile(
        "mma.sync.aligned.m16n8k16.row.col.f32.bf16.bf16.f32 "
        "{%0,%1,%2,%3}, {%4,%5,%6,%7}, {%8,%9}, {%0,%1,%2,%3};"
        : "+f"(c[0]), "+f"(c[1]), "+f"(c[2]), "+f"(c[3])
        : "r"(a[0]), "r"(a[1]), "r"(a[2]), "r"(a[3]), "r"(b0), "r"(b1));
}

#define BAR_SYNC(id)   asm volatile("bar.sync %0, 512;"   :: "r"(id) : "memory")
#define BAR_ARRIVE(id) asm volatile("bar.arrive %0, 512;" :: "r"(id) : "memory")

// bf16 2-term split: p1 = bf16x2(a0,a1) (lo=a0), p2 = bf16x2 of residuals
__device__ __forceinline__ void bsplit(float a0, float a1, unsigned& p1, unsigned& p2) {
    asm("cvt.rn.bf16x2.f32 %0, %2, %1;" : "=r"(p1) : "f"(a0), "f"(a1));
    float b0 = __uint_as_float(p1 << 16);
    float b1 = __uint_as_float(p1 & 0xffff0000u);
    float r0 = a0 - b0, r1 = a1 - b1;
    asm("cvt.rn.bf16x2.f32 %0, %2, %1;" : "=r"(p2) : "f"(r0), "f"(r1));
}

// ---------------- pack adjacency (int4 + nibble shuffle) ----------------
__global__ void k_pack(const int* __restrict__ adj) {
    int tid = threadIdx.x;
    int lane = tid & 31, wid = tid >> 5;
    int warp_g = blockIdx.x * 8 + wid;
    const int4* src = (const int4*)adj;
    int word0 = warp_g * 16;
#pragma unroll
    for (int t = 0; t < 4; t++) {
        int w4 = word0 + t*4;
        int4 v = src[(size_t)w4*8 + lane];
        unsigned nib = ((v.x>0)?1u:0u) | ((v.y>0)?2u:0u)
                     | ((v.z>0)?4u:0u) | ((v.w>0)?8u:0u);
        unsigned val = nib << ((lane & 7) * 4);
        val |= __shfl_xor_sync(0xffffffffu, val, 1);
        val |= __shfl_xor_sync(0xffffffffu, val, 2);
        val |= __shfl_xor_sync(0xffffffffu, val, 4);
        if ((lane & 7) == 0) g_adj[w4 + (lane >> 3)] = val;
    }
}

// ---------------- h = x@W -> hT bf16 splits + s/exp arrays ----------------
__global__ void k_h(const float* __restrict__ x, const float* __restrict__ W,
                    const float* __restrict__ a_vec) {
    __shared__ float xs[32*128];
    int tid = threadIdx.x;
    int row0 = blockIdx.x * 32;
    for (int i = tid; i < 32*128; i += 128) xs[i] = x[(size_t)row0*128 + i];
    __syncthreads();
    float acc[32];
#pragma unroll
    for (int r = 0; r < 32; r++) acc[r] = 0.f;
#pragma unroll 2
    for (int k = 0; k < 128; k++) {
        float wv = W[k*128 + tid];
#pragma unroll
        for (int r = 0; r < 32; r++) acc[r] += xs[r*128 + k] * wv;
    }
    int b = row0 >> 11;
    int mbase = row0 & 2047;
    {
        unsigned u1[16], u2[16];
#pragma unroll
        for (int k = 0; k < 16; k++) bsplit(acc[2*k], acc[2*k+1], u1[k], u2[k]);
        size_t base = ((size_t)(b*DD + tid) * NN + mbase) >> 1;
        uint4* d1 = (uint4*)((unsigned*)g_hT1 + base);
        uint4* d2 = (uint4*)((unsigned*)g_hT2 + base);
#pragma unroll
        for (int k = 0; k < 4; k++) {
            d1[k] = *(uint4*)(u1 + 4*k);
            d2[k] = *(uint4*)(u2 + 4*k);
        }
    }
    __syncthreads();
#pragma unroll
    for (int r = 0; r < 32; r++) xs[r*128 + tid] = acc[r];
    __syncthreads();
    int warp = tid >> 5, lane = tid & 31;
    float4 a14 = *(const float4*)(a_vec + lane*4);
    float4 a24 = *(const float4*)(a_vec + 128 + lane*4);
#pragma unroll
    for (int k = 0; k < 8; k++) {
        int r = warp*8 + k;
        float4 hv = *(const float4*)(xs + r*128 + lane*4);
        float s1 = hv.x*a14.x + hv.y*a14.y + hv.z*a14.z + hv.w*a14.w;
        float s2 = hv.x*a24.x + hv.y*a24.y + hv.z*a24.z + hv.w*a24.w;
#pragma unroll
        for (int o = 16; o; o >>= 1) {
            s1 += __shfl_xor_sync(0xffffffffu, s1, o);
            s2 += __shfl_xor_sync(0xffffffffu, s2, o);
        }
        if (lane == 0) {
            int gr = row0 + r;
            g_eA[gr] = __expf(s1);
            g_eC[gr] = __expf(NEG * s1);
            g_e12[gr] = make_float2(__expf(s2), __expf(NEG * s2));
        }
    }
}

// ---------------- smem layout (1 CTA/SM) — machine-checked ----------------
#define SM_A    0u          // 2 bufs x 32 KB  (A1 +0, A2 +16384 within buf)
#define SM_B    65536u      // 2 bufs x 32 KB  (B1 +0, B2 +16384 within buf)
#define SM_E12  131072u     // 16 KB
#define SM_ADJ  147456u     // 32 KB (128 rows x 64 words)
#define SM_ROW  180224u     // Ai/Ci/Rv: 3 x 128 floats
#define SM_TOTAL (180224u + 1536u)

static_assert(SM_B   >= SM_A   + 2*32768u, "A overlaps B");
static_assert(SM_E12 >= SM_B   + 2*32768u, "B overlaps E12");
static_assert(SM_ADJ >= SM_E12 + 16384u,   "E12 overlaps ADJ");
static_assert(SM_ROW >= SM_ADJ + (unsigned)(TILE_N*64*4), "ADJ overlaps ROW");
static_assert(SM_TOTAL >= SM_ROW + 3u*TILE_N*4u, "ROW overflows total");
static_assert(SM_TOTAL <= 227u*1024u, "smem over limit");

#define BUFSTRIDE 32768u

// ---------------- warp-specialized softmax + alpha + HMMA alpha@h ----------------
// grid (16, 8), block 512: warps 0-7 MMA consumers, warps 8-15 producers
__global__ void __launch_bounds__(512, 1) k_main(float* __restrict__ out,
                                                 float* __restrict__ alpha) {
    extern __shared__ __align__(1024) char smem[];
    uint32_t sb = smem_to_u32(smem);
    int tid = threadIdx.x, wid = tid >> 5, lane = tid & 31;
    int b = blockIdx.y, n0 = blockIdx.x * TILE_N;

    float*    e12f = (float*)(smem + SM_E12);
    unsigned* adjs = (unsigned*)(smem + SM_ADJ);
    float* AiSh = (float*)(smem + SM_ROW);
    float* CiSh = AiSh + TILE_N;
    float* RvSh = CiSh + TILE_N;

    // stage e12 (16KB) and adj (32KB)
    {
        const uint4* s = (const uint4*)(g_e12 + b*NN);
        uint4* d = (uint4*)e12f;
#pragma unroll
        for (int k = 0; k < 2; k++) d[tid + k*512] = s[tid + k*512];
    }
    {
        const uint4* s = (const uint4*)(g_adj + (size_t)n0*64);
        uint4* d = (uint4*)adjs;
#pragma unroll
        for (int k = 0; k < 4; k++) d[tid + k*512] = s[tid + k*512];
    }
    if (tid < TILE_N) {
        AiSh[tid] = g_eA[b*NN + n0 + tid];
        CiSh[tid] = g_eC[b*NN + n0 + tid];
    }
    __syncthreads();

    // ---- denominators: all 16 warps, 8 rows each ----
#pragma unroll 1
    for (int k = 0; k < 8; k++) {
        int r = wid*8 + k;
        float Ai = AiSh[r], Ci = CiSh[r];
        const unsigned* arow = adjs + r*64;
        float sum = 0.f;
#pragma unroll 4
        for (int i2 = 0; i2 < 32; i2++) {
            float4 ev = *(const float4*)(e12f + i2*128 + lane*4);
            unsigned bits = arow[i2*2 + (lane >> 4)];
            unsigned bp = (lane & 15) * 2;
            float nu0 = fmaxf(Ai*ev.x, Ci*ev.y);
            float nu1 = fmaxf(Ai*ev.z, Ci*ev.w);
            sum += ((bits >> bp) & 1u) ? nu0 : 0.f;
            sum += ((bits >> (bp+1)) & 1u) ? nu1 : 0.f;
        }
#pragma unroll
        for (int o = 16; o; o >>= 1) sum += __shfl_xor_sync(0xffffffffu, sum, o);
        if (lane == 0) RvSh[r] = 1.f / sum;
    }
    __syncthreads();

    if (tid < 256) {
        // =================== CONSUMERS (warps 0-7) ===================
        int n0w = (wid >> 2) * 64, d0w = (wid & 3) * 32;
        int arow_l = lane & 15;
        unsigned acol_l = (lane >> 4) * 16;
        int brow_l = (lane & 7) + ((lane >> 4) << 3);
        unsigned bcol_l = ((lane >> 3) & 1) * 16;
        unsigned a_xor = (unsigned)((arow_l & 7) << 4);
        unsigned b_xor = (unsigned)((brow_l & 7) << 4);
        uint32_t a_row = sb + SM_A + (unsigned)((n0w + arow_l) * 128);
        uint32_t b_row = sb + SM_B + (unsigned)((d0w + brow_l) * 128);

        float acc[4][4][4];
#pragma unroll
        for (int i = 0; i < 4; i++)
#pragma unroll
            for (int j = 0; j < 4; j++)
#pragma unroll
                for (int k = 0; k < 4; k++) acc[i][j][k] = 0.f;

        for (int c = 0; c < NCHUNKS; c++) {
            unsigned buf = (unsigned)(c & 1) * BUFSTRIDE;
            BAR_SYNC(1 + (c & 1));          // wait FULL[buf]
            uint32_t ab = a_row + buf, bb2 = b_row + buf;
#pragma unroll
            for (int ks = 0; ks < 4; ks++) {
                unsigned acol = (acol_l + ks*32) ^ a_xor;
                unsigned bcol = (bcol_l + ks*32) ^ b_xor;
                uint32_t af[4][4], b1f[2][4], b2f[2][4];
#pragma unroll
                for (int ng = 0; ng < 4; ng++) ldsm4(af[ng], ab + ng*2048 + acol);
#pragma unroll
                for (int dg = 0; dg < 2; dg++) {
                    ldsm4(b1f[dg], bb2 + dg*2048 + bcol);
                    ldsm4(b2f[dg], bb2 + dg*2048 + bcol + 16384u);
                }
                // term 1: a1*h1
#pragma unroll
                for (int ng = 0; ng < 4; ng++)
#pragma unroll
                    for (int dg = 0; dg < 2; dg++) {
                        mma_bf16(acc[ng][dg*2+0], af[ng], b1f[dg][0], b1f[dg][1]);
                        mma_bf16(acc[ng][dg*2+1], af[ng], b1f[dg][2], b1f[dg][3]);
                    }
                // term 2: a1*h2
#pragma unroll
                for (int ng = 0; ng < 4; ng++)
#pragma unroll
                    for (int dg = 0; dg < 2; dg++) {
                        mma_bf16(acc[ng][dg*2+0], af[ng], b2f[dg][0], b2f[dg][1]);
                        mma_bf16(acc[ng][dg*2+1], af[ng], b2f[dg][2], b2f[dg][3]);
                    }
                // reload A residual, term 3: a2*h1
#pragma unroll
                for (int ng = 0; ng < 4; ng++) ldsm4(af[ng], ab + ng*2048 + acol + 16384u);
#pragma unroll
                for (int ng = 0; ng < 4; ng++)
#pragma unroll
                    for (int dg = 0; dg < 2; dg++) {
                        mma_bf16(acc[ng][dg*2+0], af[ng], b1f[dg][0], b1f[dg][1]);
                        mma_bf16(acc[ng][dg*2+1], af[ng], b1f[dg][2], b1f[dg][3]);
                    }
            }
            BAR_ARRIVE(3 + (c & 1));        // signal EMPTY[buf]
        }

        // epilogue
#pragma unroll
        for (int ng = 0; ng < 4; ng++) {
#pragma unroll
            for (int dt = 0; dt < 4; dt++) {
                int r = n0 + n0w + ng*16 + (lane >> 2);
                int col = d0w + dt*8 + (lane & 3)*2;
                float* p = out + ((size_t)(b*NN + r))*DD + col;
                *(float2*)p = make_float2(acc[ng][dt][0], acc[ng][dt][1]);
                *(float2*)(p + 8*DD) = make_float2(acc[ng][dt][2], acc[ng][dt][3]);
            }
        }
    } else {
        // =================== PRODUCERS (warps 8-15) ===================
        int p = tid - 256;
        int pw = p >> 5;                  // producer warp 0..7
        int s = p & 1, r = p >> 1;        // B staging: split s, d-row r
        const unsigned short* gsrc = s ? g_hT2 : g_hT1;
        const uint4* grow = (const uint4*)(gsrc + ((size_t)(b*128 + r)) * NN);
        unsigned b_xor_st = (unsigned)((r & 7) << 4);
        unsigned bst_off = SM_B + (unsigned)(s*16384 + r*128);

        // coalesced alpha mapping: warp owns rows pw*16..pw*16+15
        int q = lane & 15, half = lane >> 4;

        // prefetch chunk 0 B
        uint4 v[8];
#pragma unroll
        for (int i = 0; i < 8; i++) v[i] = grow[i];

        for (int c = 0; c < NCHUNKS; c++) {
            unsigned buf = (unsigned)(c & 1) * BUFSTRIDE;
            if (c >= 2) BAR_SYNC(3 + (c & 1));    // wait EMPTY[buf]
            // STS B
#pragma unroll
            for (int i = 0; i < 8; i++)
                *(uint4*)(smem + bst_off + buf + ((unsigned)(i*16) ^ b_xor_st)) = v[i];
            // prefetch next chunk
            if (c + 1 < NCHUNKS) {
#pragma unroll
                for (int i = 0; i < 8; i++) v[i] = grow[(c+1)*8 + i];
            }
            // alpha: COALESCED — iter i: rows pw*16+2i+half, m = m0 + q*4
            int m0 = c * KCHUNK;
#pragma unroll
            for (int i = 0; i < 8; i++) {
                int rr = pw*16 + i*2 + half;
                float Ai = AiSh[rr], Ci = CiSh[rr], Rv = RvSh[rr];
                int mloc = q*4;
                int m = m0 + mloc;
                float4 e01 = *(const float4*)(e12f + 2*m);
                float4 e23 = *(const float4*)(e12f + 2*m + 4);
                float n0v = fmaxf(Ai*e01.x, Ci*e01.y);
                float n1v = fmaxf(Ai*e01.z, Ci*e01.w);
                float n2v = fmaxf(Ai*e23.x, Ci*e23.y);
                float n3v = fmaxf(Ai*e23.z, Ci*e23.w);
                unsigned bits = adjs[rr*64 + c*2 + (q >> 3)];
                unsigned bp = (unsigned)((q & 7) * 4);
                float a0 = ((bits >> (bp+0)) & 1u) ? n0v*Rv : 0.f;
                float a1 = ((bits >> (bp+1)) & 1u) ? n1v*Rv : 0.f;
                float a2 = ((bits >> (bp+2)) & 1u) ? n2v*Rv : 0.f;
                float a3 = ((bits >> (bp+3)) & 1u) ? n3v*Rv : 0.f;
                __stwt((float4*)(alpha + ((size_t)(b*NN + n0 + rr))*NN + m),
                       make_float4(a0, a1, a2, a3));
                unsigned p1a, p2a, p1b, p2b;
                bsplit(a0, a1, p1a, p2a);
                bsplit(a2, a3, p1b, p2b);
                unsigned so = SW128((unsigned)(rr*128 + mloc*2));
                *(uint2*)(smem + SM_A + buf + so)          = make_uint2(p1a, p1b);
                *(uint2*)(smem + SM_A + buf + 16384u + so) = make_uint2(p2a, p2b);
            }
            __threadfence_block();
            BAR_ARRIVE(1 + (c & 1));              // signal FULL[buf]
        }
    }
}

// ---------------- launch ----------------
extern "C" void kernel_launch(void* const* d_in, const int* in_sizes, int n_in,
                              void* d_out, int out_size) {
    const float* x    = (const float*)d_in[0];
    const int*   adj  = (const int*)  d_in[1];
    const float* W    = (const float*)d_in[2];
    const float* avec = (const float*)d_in[3];
    float* out   = (float*)d_out;
    float* alpha = out + (size_t)BN*DD;

    cudaFuncSetAttribute(k_main, cudaFuncAttributeMaxDynamicSharedMemorySize,
                         SM_TOTAL);

    k_pack<<<1024, 256>>>(adj);
    k_h<<<BN/32, 128>>>(x, W, avec);
    dim3 grid(NN/TILE_N, BB);
    k_main<<<grid, 512, SM_TOTAL>>>(out, alpha);
}

// round 15
// speedup vs baseline: 1.1996x; 1.0427x over previous
#include <cuda_runtime.h>
#include <cuda_bf16.h>
#include <cstdint>

#define BB 8
#define NN 2048
#define DD 128
#define NEG 0.2f
#define BN (BB*NN)

#define KCHUNK 64
#define NCHUNKS (NN/KCHUNK)   // 32
#define TILE_N 64

// ---------------- scratch (device globals) ----------------
__device__ __align__(16) unsigned short g_hT1[(size_t)BB*DD*NN];  // bf16 hi part of h^T [b][d][m]
__device__ __align__(16) unsigned short g_hT2[(size_t)BB*DD*NN];  // bf16 residual part
__device__ __align__(16) float  g_eA[BN];              // exp(s_i)
__device__ __align__(16) float  g_eC[BN];              // exp(0.2 s_i)
__device__ __align__(16) float2 g_e12[BN];             // {exp(s_j), exp(0.2 s_j)}
__device__ __align__(16) unsigned g_adj[NN*(NN/32)];   // packed adjacency bitmask

// ---------------- helpers ----------------
__device__ __forceinline__ uint32_t smem_to_u32(const void* p) {
    uint32_t a;
    asm("{ .reg .u64 t; cvta.to.shared.u64 t, %1; cvt.u32.u64 %0, t; }"
        : "=r"(a) : "l"(p));
    return a;
}
#define SW128(off) ((off) ^ (((off) >> 3) & 0x70))

__device__ __forceinline__ void ldsm4(uint32_t* r, uint32_t addr) {
    asm volatile("ldmatrix.sync.aligned.m8n8.x4.shared.b16 {%0,%1,%2,%3}, [%4];"
        : "=r"(r[0]), "=r"(r[1]), "=r"(r[2]), "=r"(r[3]) : "r"(addr));
}
__device__ __forceinline__ void mma_bf16(float* c, const uint32_t* a,
                                         uint32_t b0, uint32_t b1) {
    asm volatile(
        "mma.sync.aligned.m16n8k16.row.col.f32.bf16.bf16.f32 "
        "{%0,%1,%2,%3}, {%4,%5,%6,%7}, {%8,%9}, {%0,%1,%2,%3};"
        : "+f"(c[0]), "+f"(c[1]), "+f"(c[2]), "+f"(c[3])
        : "r"(a[0]), "r"(a[1]), "r"(a[2]), "r"(a[3]), "r"(b0), "r"(b1));
}

// bf16 2-term split: p1 = bf16x2(a0,a1) (lo=a0), p2 = bf16x2 of residuals
__device__ __forceinline__ void bsplit(float a0, float a1, unsigned& p1, unsigned& p2) {
    asm("cvt.rn.bf16x2.f32 %0, %2, %1;" : "=r"(p1) : "f"(a0), "f"(a1));
    float b0 = __uint_as_float(p1 << 16);
    float b1 = __uint_as_float(p1 & 0xffff0000u);
    float r0 = a0 - b0, r1 = a1 - b1;
    asm("cvt.rn.bf16x2.f32 %0, %2, %1;" : "=r"(p2) : "f"(r0), "f"(r1));
}

// ---------------- pack adjacency (int4 + nibble shuffle) ----------------
__global__ void k_pack(const int* __restrict__ adj) {
    int tid = threadIdx.x;
    int lane = tid & 31, wid = tid >> 5;
    int warp_g = blockIdx.x * 8 + wid;
    const int4* src = (const int4*)adj;
    int word0 = warp_g * 16;
#pragma unroll
    for (int t = 0; t < 4; t++) {
        int w4 = word0 + t*4;
        int4 v = src[(size_t)w4*8 + lane];
        unsigned nib = ((v.x>0)?1u:0u) | ((v.y>0)?2u:0u)
                     | ((v.z>0)?4u:0u) | ((v.w>0)?8u:0u);
        unsigned val = nib << ((lane & 7) * 4);
        val |= __shfl_xor_sync(0xffffffffu, val, 1);
        val |= __shfl_xor_sync(0xffffffffu, val, 2);
        val |= __shfl_xor_sync(0xffffffffu, val, 4);
        if ((lane & 7) == 0) g_adj[w4 + (lane >> 3)] = val;
    }
}

// ---------------- h = x@W -> hT bf16 splits + s/exp arrays ----------------
__global__ void k_h(const float* __restrict__ x, const float* __restrict__ W,
                    const float* __restrict__ a_vec) {
    __shared__ float xs[32*128];
    int tid = threadIdx.x;
    int row0 = blockIdx.x * 32;
    for (int i = tid; i < 32*128; i += 128) xs[i] = x[(size_t)row0*128 + i];
    __syncthreads();
    float acc[32];
#pragma unroll
    for (int r = 0; r < 32; r++) acc[r] = 0.f;
#pragma unroll 2
    for (int k = 0; k < 128; k++) {
        float wv = W[k*128 + tid];
#pragma unroll
        for (int r = 0; r < 32; r++) acc[r] += xs[r*128 + k] * wv;
    }
    int b = row0 >> 11;
    int mbase = row0 & 2047;
    {
        unsigned u1[16], u2[16];
#pragma unroll
        for (int k = 0; k < 16; k++) bsplit(acc[2*k], acc[2*k+1], u1[k], u2[k]);
        size_t base = ((size_t)(b*DD + tid) * NN + mbase) >> 1;
        uint4* d1 = (uint4*)((unsigned*)g_hT1 + base);
        uint4* d2 = (uint4*)((unsigned*)g_hT2 + base);
#pragma unroll
        for (int k = 0; k < 4; k++) {
            d1[k] = *(uint4*)(u1 + 4*k);
            d2[k] = *(uint4*)(u2 + 4*k);
        }
    }
    __syncthreads();
#pragma unroll
    for (int r = 0; r < 32; r++) xs[r*128 + tid] = acc[r];
    __syncthreads();
    int warp = tid >> 5, lane = tid & 31;
    float4 a14 = *(const float4*)(a_vec + lane*4);
    float4 a24 = *(const float4*)(a_vec + 128 + lane*4);
#pragma unroll
    for (int k = 0; k < 8; k++) {
        int r = warp*8 + k;
        float4 hv = *(const float4*)(xs + r*128 + lane*4);
        float s1 = hv.x*a14.x + hv.y*a14.y + hv.z*a14.z + hv.w*a14.w;
        float s2 = hv.x*a24.x + hv.y*a24.y + hv.z*a24.z + hv.w*a24.w;
#pragma unroll
        for (int o = 16; o; o >>= 1) {
            s1 += __shfl_xor_sync(0xffffffffu, s1, o);
            s2 += __shfl_xor_sync(0xffffffffu, s2, o);
        }
        if (lane == 0) {
            int gr = row0 + r;
            g_eA[gr] = __expf(s1);
            g_eC[gr] = __expf(NEG * s1);
            g_e12[gr] = make_float2(__expf(s2), __expf(NEG * s2));
        }
    }
}

// ---------------- smem layout (~97 KB → 2 CTAs/SM) — machine-checked ----------------
#define SM_A    0u          // 2 bufs x 16 KB (A1 +0, A2 +8192 within buf)
#define SM_B1   32768u      // 16 KB (128 x 128B)
#define SM_B2   49152u      // 16 KB
#define SM_E12  65536u      // 16 KB
#define SM_ADJ  81920u      // 16 KB (64 rows x 64 words)
#define SM_ROW  98304u      // 3 x 64 floats
#define SM_TOTAL (98304u + 768u)

static_assert(SM_B1  >= SM_A   + 2u*16384u,  "A/B1 overlap");
static_assert(SM_B2  >= SM_B1  + 128u*128u,  "B1/B2 overlap");
static_assert(SM_E12 >= SM_B2  + 128u*128u,  "B2/E12 overlap");
static_assert(SM_ADJ >= SM_E12 + 16384u,     "E12/ADJ overlap");
static_assert(SM_ROW >= SM_ADJ + 64u*64u*4u, "ADJ/ROW overlap");
static_assert(SM_TOTAL >= SM_ROW + 3u*64u*4u, "ROW overflow");
static_assert(2u*SM_TOTAL <= 228u*1024u, "2 CTAs over smem limit");

// ---------------- pipelined softmax + alpha + HMMA alpha@h ----------------
// grid (32, 8), block 256 (8 warps), 2 CTAs/SM
// per chunk: mma(c) ; alpha(c+1)->A[buf^1] ; bar ; STS B(c+1) ; bar
__global__ void __launch_bounds__(256, 2) k_main(float* __restrict__ out,
                                                 float* __restrict__ alpha) {
    extern __shared__ __align__(1024) char smem[];
    uint32_t sb = smem_to_u32(smem);
    int tid = threadIdx.x, wid = tid >> 5, lane = tid & 31;
    int b = blockIdx.y, n0 = blockIdx.x * TILE_N;

    float*    e12f = (float*)(smem + SM_E12);
    unsigned* adjs = (unsigned*)(smem + SM_ADJ);
    float* AiSh = (float*)(smem + SM_ROW);
    float* CiSh = AiSh + TILE_N;
    float* RvSh = CiSh + TILE_N;

    // stage e12 (16KB) and adj bitmask (16KB)
    {
        const uint4* s = (const uint4*)(g_e12 + b*NN);
        uint4* d = (uint4*)e12f;
#pragma unroll
        for (int k = 0; k < 4; k++) d[tid + k*256] = s[tid + k*256];
    }
    {
        const uint4* s = (const uint4*)(g_adj + (size_t)n0*64);
        uint4* d = (uint4*)adjs;
#pragma unroll
        for (int k = 0; k < 4; k++) d[tid + k*256] = s[tid + k*256];
    }
    if (tid < TILE_N) {
        AiSh[tid] = g_eA[b*NN + n0 + tid];
        CiSh[tid] = g_eC[b*NN + n0 + tid];
    }
    __syncthreads();

    // ---- denominators (8 rows per warp) ----
#pragma unroll 1
    for (int k = 0; k < 8; k++) {
        int r = wid*8 + k;
        float Ai = AiSh[r], Ci = CiSh[r];
        const unsigned* arow = adjs + r*64;
        float sum = 0.f;
#pragma unroll 4
        for (int i2 = 0; i2 < 32; i2++) {
            float4 ev = *(const float4*)(e12f + i2*128 + lane*4);
            unsigned bits = arow[i2*2 + (lane >> 4)];
            unsigned bp = (lane & 15) * 2;
            float nu0 = fmaxf(Ai*ev.x, Ci*ev.y);
            float nu1 = fmaxf(Ai*ev.z, Ci*ev.w);
            sum += ((bits >> bp) & 1u) ? nu0 : 0.f;
            sum += ((bits >> (bp+1)) & 1u) ? nu1 : 0.f;
        }
#pragma unroll
        for (int o = 16; o; o >>= 1) sum += __shfl_xor_sync(0xffffffffu, sum, o);
        if (lane == 0) RvSh[r] = 1.f / sum;
    }
    __syncthreads();

    // coalesced alpha mapping
    int q = lane & 15, half = lane >> 4;

    // B staging via reg prefetch: 4 rows/thread/split (rows brow+32i)
    int brow = tid >> 3, bq = tid & 7;
    size_t gbase = ((size_t)(b*128 + brow))*256 + bq;     // uint4 units
    unsigned bsw = SW128((unsigned)(brow*128 + bq*16));
    const uint4* gB1 = (const uint4*)g_hT1;
    const uint4* gB2 = (const uint4*)g_hT2;

    // warp GEMM tiling: warp -> n-half 32, d-quarter 32
    int n0w = (wid >> 2) * 32, d0w = (wid & 3) * 32;
    int arow_l = lane & 15;
    unsigned acol_l = (lane >> 4) * 16;
    int brow_l = (lane & 7) + ((lane >> 4) << 3);
    unsigned bcol_l = ((lane >> 3) & 1) * 16;
    unsigned a_xor = (unsigned)((arow_l & 7) << 4);
    unsigned b_xor = (unsigned)((brow_l & 7) << 4);
    uint32_t a_row_base = sb + SM_A + (unsigned)((n0w + arow_l) * 128);
    uint32_t b_row_base = sb + SM_B1 + (unsigned)((d0w + brow_l) * 128);

    float acc[2][4][4];
#pragma unroll
    for (int i = 0; i < 2; i++)
#pragma unroll
        for (int j = 0; j < 4; j++)
#pragma unroll
            for (int k = 0; k < 4; k++) acc[i][j][k] = 0.f;

    // producer alpha lambda (chunk cc -> A buffer abuf)
    auto alpha_phase = [&](int cc, unsigned abuf) {
        int m0 = cc * KCHUNK;
#pragma unroll
        for (int i = 0; i < 4; i++) {
            int rr = wid*8 + i*2 + half;
            float Ai = AiSh[rr], Ci = CiSh[rr], Rv = RvSh[rr];
            int mloc = q*4;
            int m = m0 + mloc;
            float4 e01 = *(const float4*)(e12f + 2*m);
            float4 e23 = *(const float4*)(e12f + 2*m + 4);
            float n0v = fmaxf(Ai*e01.x, Ci*e01.y);
            float n1v = fmaxf(Ai*e01.z, Ci*e01.w);
            float n2v = fmaxf(Ai*e23.x, Ci*e23.y);
            float n3v = fmaxf(Ai*e23.z, Ci*e23.w);
            unsigned bits = adjs[rr*64 + cc*2 + (q >> 3)];
            unsigned bp = (unsigned)((q & 7) * 4);
            float a0 = ((bits >> (bp+0)) & 1u) ? n0v*Rv : 0.f;
            float a1 = ((bits >> (bp+1)) & 1u) ? n1v*Rv : 0.f;
            float a2 = ((bits >> (bp+2)) & 1u) ? n2v*Rv : 0.f;
            float a3 = ((bits >> (bp+3)) & 1u) ? n3v*Rv : 0.f;
            __stwt((float4*)(alpha + ((size_t)(b*NN + n0 + rr))*NN + m),
                   make_float4(a0, a1, a2, a3));
            unsigned p1a, p2a, p1b, p2b;
            bsplit(a0, a1, p1a, p2a);
            bsplit(a2, a3, p1b, p2b);
            unsigned so = SW128((unsigned)(rr*128 + mloc*2));
            *(uint2*)(smem + SM_A + abuf + so)         = make_uint2(p1a, p1b);
            *(uint2*)(smem + SM_A + abuf + 8192u + so) = make_uint2(p2a, p2b);
        }
    };

    // ---- prologue: B(0) + A(0) ----
    uint4 v1[4], v2[4];
#pragma unroll
    for (int i = 0; i < 4; i++) {
        v1[i] = gB1[gbase + (size_t)i*8192];
        v2[i] = gB2[gbase + (size_t)i*8192];
    }
#pragma unroll
    for (int i = 0; i < 4; i++) {
        *(uint4*)(smem + SM_B1 + bsw + i*4096) = v1[i];
        *(uint4*)(smem + SM_B2 + bsw + i*4096) = v2[i];
    }
    // prefetch B(1)
#pragma unroll
    for (int i = 0; i < 4; i++) {
        v1[i] = gB1[gbase + (size_t)i*8192 + 8];
        v2[i] = gB2[gbase + (size_t)i*8192 + 8];
    }
    alpha_phase(0, 0u);
    __syncthreads();

    for (int c = 0; c < NCHUNKS; c++) {
        unsigned abuf = (unsigned)(c & 1) * 16384u;
        // MMA(c): 4 k-steps, term-major
#pragma unroll
        for (int ks = 0; ks < 4; ks++) {
            unsigned acol = (acol_l + ks*32) ^ a_xor;
            unsigned bcol = (bcol_l + ks*32) ^ b_xor;
            uint32_t a1f[2][4], a2f[2][4], b1f[2][4], b2f[2][4];
#pragma unroll
            for (int ng = 0; ng < 2; ng++) {
                ldsm4(a1f[ng], a_row_base + abuf + ng*2048 + acol);
                ldsm4(a2f[ng], a_row_base + abuf + ng*2048 + acol + 8192u);
            }
#pragma unroll
            for (int dg = 0; dg < 2; dg++) {
                ldsm4(b1f[dg], b_row_base + dg*2048 + bcol);
                ldsm4(b2f[dg], b_row_base + dg*2048 + bcol + 16384u);
            }
#pragma unroll
            for (int ng = 0; ng < 2; ng++)
#pragma unroll
                for (int dg = 0; dg < 2; dg++) {
                    mma_bf16(acc[ng][dg*2+0], a1f[ng], b1f[dg][0], b1f[dg][1]);
                    mma_bf16(acc[ng][dg*2+1], a1f[ng], b1f[dg][2], b1f[dg][3]);
                }
#pragma unroll
            for (int ng = 0; ng < 2; ng++)
#pragma unroll
                for (int dg = 0; dg < 2; dg++) {
                    mma_bf16(acc[ng][dg*2+0], a1f[ng], b2f[dg][0], b2f[dg][1]);
                    mma_bf16(acc[ng][dg*2+1], a1f[ng], b2f[dg][2], b2f[dg][3]);
                }
#pragma unroll
            for (int ng = 0; ng < 2; ng++)
#pragma unroll
                for (int dg = 0; dg < 2; dg++) {
                    mma_bf16(acc[ng][dg*2+0], a2f[ng], b1f[dg][0], b1f[dg][1]);
                    mma_bf16(acc[ng][dg*2+1], a2f[ng], b1f[dg][2], b1f[dg][3]);
                }
        }
        // alpha(c+1) into the other A buffer — overlaps other warps' MMA
        if (c + 1 < NCHUNKS) alpha_phase(c + 1, abuf ^ 16384u);
        __syncthreads();
        // B(c+1) STS + prefetch B(c+2)
        if (c + 1 < NCHUNKS) {
#pragma unroll
            for (int i = 0; i < 4; i++) {
                *(uint4*)(smem + SM_B1 + bsw + i*4096) = v1[i];
                *(uint4*)(smem + SM_B2 + bsw + i*4096) = v2[i];
            }
            if (c + 2 < NCHUNKS) {
                size_t mo = (size_t)((c + 2) * 8);
#pragma unroll
                for (int i = 0; i < 4; i++) {
                    v1[i] = gB1[gbase + (size_t)i*8192 + mo];
                    v2[i] = gB2[gbase + (size_t)i*8192 + mo];
                }
            }
            __syncthreads();
        }
    }

    // epilogue: write out tile
#pragma unroll
    for (int ng = 0; ng < 2; ng++) {
#pragma unroll
        for (int dt = 0; dt < 4; dt++) {
            int r = n0 + n0w + ng*16 + (lane >> 2);
            int col = d0w + dt*8 + (lane & 3)*2;
            float* p = out + ((size_t)(b*NN + r))*DD + col;
            *(float2*)p = make_float2(acc[ng][dt][0], acc[ng][dt][1]);
            *(float2*)(p + 8*DD) = make_float2(acc[ng][dt][2], acc[ng][dt][3]);
        }
    }
}

// ---------------- launch ----------------
extern "C" void kernel_launch(void* const* d_in, const int* in_sizes, int n_in,
                              void* d_out, int out_size) {
    const float* x    = (const float*)d_in[0];
    const int*   adj  = (const int*)  d_in[1];
    const float* W    = (const float*)d_in[2];
    const float* avec = (const float*)d_in[3];
    float* out   = (float*)d_out;
    float* alpha = out + (size_t)BN*DD;

    cudaFuncSetAttribute(k_main, cudaFuncAttributeMaxDynamicSharedMemorySize,
                         SM_TOTAL);

    k_pack<<<1024, 256>>>(adj);
    k_h<<<BN/32, 128>>>(x, W, avec);
    dim3 grid(NN/TILE_N, BB);
    k_main<<<grid, 256, SM_TOTAL>>>(out, alpha);
}

// round 16
// speedup vs baseline: 1.3337x; 1.1117x over previous
#include <cuda_runtime.h>
#include <cuda_fp16.h>
#include <cstdint>

#define BB 8
#define NN 2048
#define DD 128
#define NEG 0.2f
#define BN (BB*NN)

#define KCHUNK 64
#define NCHUNKS (NN/KCHUNK)   // 32
#define TILE_N 64

// ---------------- scratch (device globals) ----------------
__device__ __align__(16) unsigned short g_hT1[(size_t)BB*DD*NN];  // fp16 hi part of h^T [b][d][m]
__device__ __align__(16) unsigned short g_hT2[(size_t)BB*DD*NN];  // fp16 residual part
__device__ __align__(16) float  g_eA[BN];              // exp(s_i)
__device__ __align__(16) float  g_eC[BN];              // exp(0.2 s_i)
__device__ __align__(16) float2 g_e12[BN];             // {exp(s_j), exp(0.2 s_j)}
__device__ __align__(16) unsigned g_adj[NN*(NN/32)];   // packed adjacency bitmask

// ---------------- helpers ----------------
__device__ __forceinline__ uint32_t smem_to_u32(const void* p) {
    uint32_t a;
    asm("{ .reg .u64 t; cvta.to.shared.u64 t, %1; cvt.u32.u64 %0, t; }"
        : "=r"(a) : "l"(p));
    return a;
}
#define SW128(off) ((off) ^ (((off) >> 3) & 0x70))

__device__ __forceinline__ void ldsm4(uint32_t* r, uint32_t addr) {
    asm volatile("ldmatrix.sync.aligned.m8n8.x4.shared.b16 {%0,%1,%2,%3}, [%4];"
        : "=r"(r[0]), "=r"(r[1]), "=r"(r[2]), "=r"(r[3]) : "r"(addr));
}
__device__ __forceinline__ void mma_f16(float* c, const uint32_t* a,
                                        uint32_t b0, uint32_t b1) {
    asm volatile(
        "mma.sync.aligned.m16n8k16.row.col.f32.f16.f16.f32 "
        "{%0,%1,%2,%3}, {%4,%5,%6,%7}, {%8,%9}, {%0,%1,%2,%3};"
        : "+f"(c[0]), "+f"(c[1]), "+f"(c[2]), "+f"(c[3])
        : "r"(a[0]), "r"(a[1]), "r"(a[2]), "r"(a[3]), "r"(b0), "r"(b1));
}

__device__ __forceinline__ unsigned h2bits(__half2 h) {
    unsigned u; asm("mov.b32 %0, %1;" : "=r"(u) : "r"(*(unsigned*)&h));
    return *(unsigned*)&h;
}

// fp16 2-term split of a float pair: p1 = f16x2(a0,a1), p2 = residuals
__device__ __forceinline__ void hsplit(float a0, float a1, unsigned& p1, unsigned& p2) {
    __half2 h = __floats2half2_rn(a0, a1);
    p1 = *(unsigned*)&h;
    float r0 = a0 - __low2float(h);
    float r1 = a1 - __high2float(h);
    __half2 r = __floats2half2_rn(r0, r1);
    p2 = *(unsigned*)&r;
}

// ---------------- pack adjacency (int4 + nibble shuffle) ----------------
__global__ void k_pack(const int* __restrict__ adj) {
    int tid = threadIdx.x;
    int lane = tid & 31, wid = tid >> 5;
    int warp_g = blockIdx.x * 8 + wid;
    const int4* src = (const int4*)adj;
    int word0 = warp_g * 16;
#pragma unroll
    for (int t = 0; t < 4; t++) {
        int w4 = word0 + t*4;
        int4 v = src[(size_t)w4*8 + lane];
        unsigned nib = ((v.x>0)?1u:0u) | ((v.y>0)?2u:0u)
                     | ((v.z>0)?4u:0u) | ((v.w>0)?8u:0u);
        unsigned val = nib << ((lane & 7) * 4);
        val |= __shfl_xor_sync(0xffffffffu, val, 1);
        val |= __shfl_xor_sync(0xffffffffu, val, 2);
        val |= __shfl_xor_sync(0xffffffffu, val, 4);
        if ((lane & 7) == 0) g_adj[w4 + (lane >> 3)] = val;
    }
}

// ---------------- h = x@W -> hT fp16 splits + s/exp arrays ----------------
__global__ void k_h(const float* __restrict__ x, const float* __restrict__ W,
                    const float* __restrict__ a_vec) {
    __shared__ float xs[32*128];
    int tid = threadIdx.x;
    int row0 = blockIdx.x * 32;
    for (int i = tid; i < 32*128; i += 128) xs[i] = x[(size_t)row0*128 + i];
    __syncthreads();
    float acc[32];
#pragma unroll
    for (int r = 0; r < 32; r++) acc[r] = 0.f;
#pragma unroll 2
    for (int k = 0; k < 128; k++) {
        float wv = W[k*128 + tid];
#pragma unroll
        for (int r = 0; r < 32; r++) acc[r] += xs[r*128 + k] * wv;
    }
    int b = row0 >> 11;
    int mbase = row0 & 2047;
    {
        unsigned u1[16], u2[16];
#pragma unroll
        for (int k = 0; k < 16; k++) hsplit(acc[2*k], acc[2*k+1], u1[k], u2[k]);
        size_t base = ((size_t)(b*DD + tid) * NN + mbase) >> 1;
        uint4* d1 = (uint4*)((unsigned*)g_hT1 + base);
        uint4* d2 = (uint4*)((unsigned*)g_hT2 + base);
#pragma unroll
        for (int k = 0; k < 4; k++) {
            d1[k] = *(uint4*)(u1 + 4*k);
            d2[k] = *(uint4*)(u2 + 4*k);
        }
    }
    __syncthreads();
#pragma unroll
    for (int r = 0; r < 32; r++) xs[r*128 + tid] = acc[r];
    __syncthreads();
    int warp = tid >> 5, lane = tid & 31;
    float4 a14 = *(const float4*)(a_vec + lane*4);
    float4 a24 = *(const float4*)(a_vec + 128 + lane*4);
#pragma unroll
    for (int k = 0; k < 8; k++) {
        int r = warp*8 + k;
        float4 hv = *(const float4*)(xs + r*128 + lane*4);
        float s1 = hv.x*a14.x + hv.y*a14.y + hv.z*a14.z + hv.w*a14.w;
        float s2 = hv.x*a24.x + hv.y*a24.y + hv.z*a24.z + hv.w*a24.w;
#pragma unroll
        for (int o = 16; o; o >>= 1) {
            s1 += __shfl_xor_sync(0xffffffffu, s1, o);
            s2 += __shfl_xor_sync(0xffffffffu, s2, o);
        }
        if (lane == 0) {
            int gr = row0 + r;
            g_eA[gr] = __expf(s1);
            g_eC[gr] = __expf(NEG * s1);
            g_e12[gr] = make_float2(__expf(s2), __expf(NEG * s2));
        }
    }
}

// ---------------- smem layout (~82 KB → 2 CTAs/SM) — machine-checked ----------------
#define SM_A    0u          // 2 bufs x 8 KB (single fp16 alpha tile)
#define SM_B1   16384u      // 16 KB (128 x 128B)
#define SM_B2   32768u      // 16 KB
#define SM_E12  49152u      // 16 KB
#define SM_ADJ  65536u      // 16 KB (64 rows x 64 words)
#define SM_ROW  81920u      // 3 x 64 floats
#define SM_TOTAL (81920u + 768u)

static_assert(SM_B1  >= SM_A   + 2u*8192u,   "A/B1 overlap");
static_assert(SM_B2  >= SM_B1  + 128u*128u,  "B1/B2 overlap");
static_assert(SM_E12 >= SM_B2  + 128u*128u,  "B2/E12 overlap");
static_assert(SM_ADJ >= SM_E12 + 16384u,     "E12/ADJ overlap");
static_assert(SM_ROW >= SM_ADJ + 64u*64u*4u, "ADJ/ROW overlap");
static_assert(SM_TOTAL >= SM_ROW + 3u*64u*4u, "ROW overflow");
static_assert(2u*SM_TOTAL <= 228u*1024u, "2 CTAs over smem limit");

// ---------------- pipelined softmax + alpha + HMMA alpha@h (fp16, 2-term) ----------------
// grid (32, 8), block 256 (8 warps), 2 CTAs/SM
__global__ void __launch_bounds__(256, 2) k_main(float* __restrict__ out,
                                                 float* __restrict__ alpha) {
    extern __shared__ __align__(1024) char smem[];
    uint32_t sb = smem_to_u32(smem);
    int tid = threadIdx.x, wid = tid >> 5, lane = tid & 31;
    int b = blockIdx.y, n0 = blockIdx.x * TILE_N;

    float*    e12f = (float*)(smem + SM_E12);
    unsigned* adjs = (unsigned*)(smem + SM_ADJ);
    float* AiSh = (float*)(smem + SM_ROW);
    float* CiSh = AiSh + TILE_N;
    float* RvSh = CiSh + TILE_N;

    // stage e12 (16KB) and adj bitmask (16KB)
    {
        const uint4* s = (const uint4*)(g_e12 + b*NN);
        uint4* d = (uint4*)e12f;
#pragma unroll
        for (int k = 0; k < 4; k++) d[tid + k*256] = s[tid + k*256];
    }
    {
        const uint4* s = (const uint4*)(g_adj + (size_t)n0*64);
        uint4* d = (uint4*)adjs;
#pragma unroll
        for (int k = 0; k < 4; k++) d[tid + k*256] = s[tid + k*256];
    }
    if (tid < TILE_N) {
        AiSh[tid] = g_eA[b*NN + n0 + tid];
        CiSh[tid] = g_eC[b*NN + n0 + tid];
    }
    __syncthreads();

    // ---- denominators (8 rows per warp) ----
#pragma unroll 1
    for (int k = 0; k < 8; k++) {
        int r = wid*8 + k;
        float Ai = AiSh[r], Ci = CiSh[r];
        const unsigned* arow = adjs + r*64;
        float sum = 0.f;
#pragma unroll 4
        for (int i2 = 0; i2 < 32; i2++) {
            float4 ev = *(const float4*)(e12f + i2*128 + lane*4);
            unsigned bits = arow[i2*2 + (lane >> 4)];
            unsigned bp = (lane & 15) * 2;
            float nu0 = fmaxf(Ai*ev.x, Ci*ev.y);
            float nu1 = fmaxf(Ai*ev.z, Ci*ev.w);
            sum += ((bits >> bp) & 1u) ? nu0 : 0.f;
            sum += ((bits >> (bp+1)) & 1u) ? nu1 : 0.f;
        }
#pragma unroll
        for (int o = 16; o; o >>= 1) sum += __shfl_xor_sync(0xffffffffu, sum, o);
        if (lane == 0) RvSh[r] = 1.f / sum;
    }
    __syncthreads();

    // coalesced alpha mapping
    int q = lane & 15, half = lane >> 4;

    // B staging via reg prefetch: 4 rows/thread/split (rows brow+32i)
    int brow = tid >> 3, bq = tid & 7;
    size_t gbase = ((size_t)(b*128 + brow))*256 + bq;     // uint4 units
    unsigned bsw = SW128((unsigned)(brow*128 + bq*16));
    const uint4* gB1 = (const uint4*)g_hT1;
    const uint4* gB2 = (const uint4*)g_hT2;

    // warp GEMM tiling: warp -> n-half 32, d-quarter 32
    int n0w = (wid >> 2) * 32, d0w = (wid & 3) * 32;
    int arow_l = lane & 15;
    unsigned acol_l = (lane >> 4) * 16;
    int brow_l = (lane & 7) + ((lane >> 4) << 3);
    unsigned bcol_l = ((lane >> 3) & 1) * 16;
    unsigned a_xor = (unsigned)((arow_l & 7) << 4);
    unsigned b_xor = (unsigned)((brow_l & 7) << 4);
    uint32_t a_row_base = sb + SM_A + (unsigned)((n0w + arow_l) * 128);
    uint32_t b_row_base = sb + SM_B1 + (unsigned)((d0w + brow_l) * 128);

    float acc[2][4][4];
#pragma unroll
    for (int i = 0; i < 2; i++)
#pragma unroll
        for (int j = 0; j < 4; j++)
#pragma unroll
            for (int k = 0; k < 4; k++) acc[i][j][k] = 0.f;

    // producer alpha lambda (chunk cc -> A buffer abuf); single fp16 alpha
    auto alpha_phase = [&](int cc, unsigned abuf) {
        int m0 = cc * KCHUNK;
#pragma unroll
        for (int i = 0; i < 4; i++) {
            int rr = wid*8 + i*2 + half;
            float Ai = AiSh[rr], Ci = CiSh[rr], Rv = RvSh[rr];
            int mloc = q*4;
            int m = m0 + mloc;
            float4 e01 = *(const float4*)(e12f + 2*m);
            float4 e23 = *(const float4*)(e12f + 2*m + 4);
            float n0v = fmaxf(Ai*e01.x, Ci*e01.y);
            float n1v = fmaxf(Ai*e01.z, Ci*e01.w);
            float n2v = fmaxf(Ai*e23.x, Ci*e23.y);
            float n3v = fmaxf(Ai*e23.z, Ci*e23.w);
            unsigned bits = adjs[rr*64 + cc*2 + (q >> 3)];
            unsigned bp = (unsigned)((q & 7) * 4);
            float a0 = ((bits >> (bp+0)) & 1u) ? n0v*Rv : 0.f;
            float a1 = ((bits >> (bp+1)) & 1u) ? n1v*Rv : 0.f;
            float a2 = ((bits >> (bp+2)) & 1u) ? n2v*Rv : 0.f;
            float a3 = ((bits >> (bp+3)) & 1u) ? n3v*Rv : 0.f;
            __stwt((float4*)(alpha + ((size_t)(b*NN + n0 + rr))*NN + m),
                   make_float4(a0, a1, a2, a3));
            __half2 pa = __floats2half2_rn(a0, a1);
            __half2 pb = __floats2half2_rn(a2, a3);
            unsigned so = SW128((unsigned)(rr*128 + mloc*2));
            *(uint2*)(smem + SM_A + abuf + so) =
                make_uint2(*(unsigned*)&pa, *(unsigned*)&pb);
        }
    };

    // ---- prologue: B(0) + A(0) ----
    uint4 v1[4], v2[4];
#pragma unroll
    for (int i = 0; i < 4; i++) {
        v1[i] = gB1[gbase + (size_t)i*8192];
        v2[i] = gB2[gbase + (size_t)i*8192];
    }
#pragma unroll
    for (int i = 0; i < 4; i++) {
        *(uint4*)(smem + SM_B1 + bsw + i*4096) = v1[i];
        *(uint4*)(smem + SM_B2 + bsw + i*4096) = v2[i];
    }
    // prefetch B(1)
#pragma unroll
    for (int i = 0; i < 4; i++) {
        v1[i] = gB1[gbase + (size_t)i*8192 + 8];
        v2[i] = gB2[gbase + (size_t)i*8192 + 8];
    }
    alpha_phase(0, 0u);
    __syncthreads();

    for (int c = 0; c < NCHUNKS; c++) {
        unsigned abuf = (unsigned)(c & 1) * 8192u;
        // MMA(c): 4 k-steps, 2 terms (a@h1, a@h2), A fragments reused
#pragma unroll
        for (int ks = 0; ks < 4; ks++) {
            unsigned acol = (acol_l + ks*32) ^ a_xor;
            unsigned bcol = (bcol_l + ks*32) ^ b_xor;
            uint32_t af[2][4], b1f[2][4], b2f[2][4];
#pragma unroll
            for (int ng = 0; ng < 2; ng++)
                ldsm4(af[ng], a_row_base + abuf + ng*2048 + acol);
#pragma unroll
            for (int dg = 0; dg < 2; dg++) {
                ldsm4(b1f[dg], b_row_base + dg*2048 + bcol);
                ldsm4(b2f[dg], b_row_base + dg*2048 + bcol + 16384u);
            }
#pragma unroll
            for (int ng = 0; ng < 2; ng++)
#pragma unroll
                for (int dg = 0; dg < 2; dg++) {
                    mma_f16(acc[ng][dg*2+0], af[ng], b1f[dg][0], b1f[dg][1]);
                    mma_f16(acc[ng][dg*2+1], af[ng], b1f[dg][2], b1f[dg][3]);
                }
#pragma unroll
            for (int ng = 0; ng < 2; ng++)
#pragma unroll
                for (int dg = 0; dg < 2; dg++) {
                    mma_f16(acc[ng][dg*2+0], af[ng], b2f[dg][0], b2f[dg][1]);
                    mma_f16(acc[ng][dg*2+1], af[ng], b2f[dg][2], b2f[dg][3]);
                }
        }
        // alpha(c+1) into the other A buffer — overlaps other warps' MMA
        if (c + 1 < NCHUNKS) alpha_phase(c + 1, abuf ^ 8192u);
        __syncthreads();
        // B(c+1) STS + prefetch B(c+2)
        if (c + 1 < NCHUNKS) {
#pragma unroll
            for (int i = 0; i < 4; i++) {
                *(uint4*)(smem + SM_B1 + bsw + i*4096) = v1[i];
                *(uint4*)(smem + SM_B2 + bsw + i*4096) = v2[i];
            }
            if (c + 2 < NCHUNKS) {
                size_t mo = (size_t)((c + 2) * 8);
#pragma unroll
                for (int i = 0; i < 4; i++) {
                    v1[i] = gB1[gbase + (size_t)i*8192 + mo];
                    v2[i] = gB2[gbase + (size_t)i*8192 + mo];
                }
            }
            __syncthreads();
        }
    }

    // epilogue: write out tile
#pragma unroll
    for (int ng = 0; ng < 2; ng++) {
#pragma unroll
        for (int dt = 0; dt < 4; dt++) {
            int r = n0 + n0w + ng*16 + (lane >> 2);
            int col = d0w + dt*8 + (lane & 3)*2;
            float* p = out + ((size_t)(b*NN + r))*DD + col;
            *(float2*)p = make_float2(acc[ng][dt][0], acc[ng][dt][1]);
            *(float2*)(p + 8*DD) = make_float2(acc[ng][dt][2], acc[ng][dt][3]);
        }
    }
}

// ---------------- launch ----------------
extern "C" void kernel_launch(void* const* d_in, const int* in_sizes, int n_in,
                              void* d_out, int out_size) {
    const float* x    = (const float*)d_in[0];
    const int*   adj  = (const int*)  d_in[1];
    const float* W    = (const float*)d_in[2];
    const float* avec = (const float*)d_in[3];
    float* out   = (float*)d_out;
    float* alpha = out + (size_t)BN*DD;

    cudaFuncSetAttribute(k_main, cudaFuncAttributeMaxDynamicSharedMemorySize,
                         SM_TOTAL);

    k_pack<<<1024, 256>>>(adj);
    k_h<<<BN/32, 128>>>(x, W, avec);
    dim3 grid(NN/TILE_N, BB);
    k_main<<<grid, 256, SM_TOTAL>>>(out, alpha);
}

// round 17
// speedup vs baseline: 1.4522x; 1.0889x over previous
#include <cuda_runtime.h>
#include <cuda_fp16.h>
#include <cstdint>

#define BB 8
#define NN 2048
#define DD 128
#define NEG 0.2f
#define BN (BB*NN)

#define KCHUNK 64
#define NCHUNKS (NN/KCHUNK)   // 32
#define TILE_N 64

// ---------------- scratch (device globals) ----------------
__device__ __align__(16) unsigned short g_hT[(size_t)BB*DD*NN];   // fp16 h^T [b][d][m]
__device__ __align__(16) float  g_eA[BN];              // exp(s_i)
__device__ __align__(16) float  g_eC[BN];              // exp(0.2 s_i)
__device__ __align__(16) float2 g_e12[BN];             // {exp(s_j), exp(0.2 s_j)}
__device__ __align__(16) unsigned g_adj[NN*(NN/32)];   // packed adjacency bitmask

// ---------------- helpers ----------------
__device__ __forceinline__ uint32_t smem_to_u32(const void* p) {
    uint32_t a;
    asm("{ .reg .u64 t; cvta.to.shared.u64 t, %1; cvt.u32.u64 %0, t; }"
        : "=r"(a) : "l"(p));
    return a;
}
#define SW128(off) ((off) ^ (((off) >> 3) & 0x70))

__device__ __forceinline__ void ldsm4(uint32_t* r, uint32_t addr) {
    asm volatile("ldmatrix.sync.aligned.m8n8.x4.shared.b16 {%0,%1,%2,%3}, [%4];"
        : "=r"(r[0]), "=r"(r[1]), "=r"(r[2]), "=r"(r[3]) : "r"(addr));
}
__device__ __forceinline__ void mma_f16(float* c, const uint32_t* a,
                                        uint32_t b0, uint32_t b1) {
    asm volatile(
        "mma.sync.aligned.m16n8k16.row.col.f32.f16.f16.f32 "
        "{%0,%1,%2,%3}, {%4,%5,%6,%7}, {%8,%9}, {%0,%1,%2,%3};"
        : "+f"(c[0]), "+f"(c[1]), "+f"(c[2]), "+f"(c[3])
        : "r"(a[0]), "r"(a[1]), "r"(a[2]), "r"(a[3]), "r"(b0), "r"(b1));
}

// ---------------- pack adjacency (int4 + nibble shuffle) ----------------
__global__ void k_pack(const int* __restrict__ adj) {
    int tid = threadIdx.x;
    int lane = tid & 31, wid = tid >> 5;
    int warp_g = blockIdx.x * 8 + wid;
    const int4* src = (const int4*)adj;
    int word0 = warp_g * 16;
#pragma unroll
    for (int t = 0; t < 4; t++) {
        int w4 = word0 + t*4;
        int4 v = src[(size_t)w4*8 + lane];
        unsigned nib = ((v.x>0)?1u:0u) | ((v.y>0)?2u:0u)
                     | ((v.z>0)?4u:0u) | ((v.w>0)?8u:0u);
        unsigned val = nib << ((lane & 7) * 4);
        val |= __shfl_xor_sync(0xffffffffu, val, 1);
        val |= __shfl_xor_sync(0xffffffffu, val, 2);
        val |= __shfl_xor_sync(0xffffffffu, val, 4);
        if ((lane & 7) == 0) g_adj[w4 + (lane >> 3)] = val;
    }
}

// ---------------- h = x@W -> hT fp16 + s/exp arrays ----------------
__global__ void k_h(const float* __restrict__ x, const float* __restrict__ W,
                    const float* __restrict__ a_vec) {
    __shared__ float xs[32*128];
    int tid = threadIdx.x;
    int row0 = blockIdx.x * 32;
    for (int i = tid; i < 32*128; i += 128) xs[i] = x[(size_t)row0*128 + i];
    __syncthreads();
    float acc[32];
#pragma unroll
    for (int r = 0; r < 32; r++) acc[r] = 0.f;
#pragma unroll 2
    for (int k = 0; k < 128; k++) {
        float wv = W[k*128 + tid];
#pragma unroll
        for (int r = 0; r < 32; r++) acc[r] += xs[r*128 + k] * wv;
    }
    int b = row0 >> 11;
    int mbase = row0 & 2047;
    {
        unsigned u1[16];
#pragma unroll
        for (int k = 0; k < 16; k++) {
            __half2 h = __floats2half2_rn(acc[2*k], acc[2*k+1]);
            u1[k] = *(unsigned*)&h;
        }
        size_t base = ((size_t)(b*DD + tid) * NN + mbase) >> 1;
        uint4* d1 = (uint4*)((unsigned*)g_hT + base);
#pragma unroll
        for (int k = 0; k < 4; k++) d1[k] = *(uint4*)(u1 + 4*k);
    }
    __syncthreads();
#pragma unroll
    for (int r = 0; r < 32; r++) xs[r*128 + tid] = acc[r];
    __syncthreads();
    int warp = tid >> 5, lane = tid & 31;
    float4 a14 = *(const float4*)(a_vec + lane*4);
    float4 a24 = *(const float4*)(a_vec + 128 + lane*4);
#pragma unroll
    for (int k = 0; k < 8; k++) {
        int r = warp*8 + k;
        float4 hv = *(const float4*)(xs + r*128 + lane*4);
        float s1 = hv.x*a14.x + hv.y*a14.y + hv.z*a14.z + hv.w*a14.w;
        float s2 = hv.x*a24.x + hv.y*a24.y + hv.z*a24.z + hv.w*a24.w;
#pragma unroll
        for (int o = 16; o; o >>= 1) {
            s1 += __shfl_xor_sync(0xffffffffu, s1, o);
            s2 += __shfl_xor_sync(0xffffffffu, s2, o);
        }
        if (lane == 0) {
            int gr = row0 + r;
            g_eA[gr] = __expf(s1);
            g_eC[gr] = __expf(NEG * s1);
            g_e12[gr] = make_float2(__expf(s2), __expf(NEG * s2));
        }
    }
}

// ---------------- smem layout (~81 KB → 2 CTAs/SM) — machine-checked ----------------
#define SM_A    0u          // 2 bufs x 8 KB (fp16 alpha tile)
#define SM_B    16384u      // 2 bufs x 16 KB (fp16 h tile, 128 rows x 128B)
#define SM_E12  49152u      // 16 KB
#define SM_ADJ  65536u      // 16 KB (64 rows x 64 words)
#define SM_ROW  81920u      // 3 x 64 floats
#define SM_TOTAL (81920u + 768u)

static_assert(SM_B   >= SM_A   + 2u*8192u,   "A/B overlap");
static_assert(SM_E12 >= SM_B   + 2u*16384u,  "B/E12 overlap");
static_assert(SM_ADJ >= SM_E12 + 16384u,     "E12/ADJ overlap");
static_assert(SM_ROW >= SM_ADJ + 64u*64u*4u, "ADJ/ROW overlap");
static_assert(SM_TOTAL >= SM_ROW + 3u*64u*4u, "ROW overflow");
static_assert(2u*SM_TOTAL <= 228u*1024u, "2 CTAs over smem limit");

// ---------------- pipelined softmax + alpha + HMMA alpha@h (pure fp16) ----------------
// grid (32, 8), block 256 (8 warps), 2 CTAs/SM, ONE barrier per chunk
__global__ void __launch_bounds__(256, 2) k_main(float* __restrict__ out,
                                                 float* __restrict__ alpha) {
    extern __shared__ __align__(1024) char smem[];
    uint32_t sb = smem_to_u32(smem);
    int tid = threadIdx.x, wid = tid >> 5, lane = tid & 31;
    int b = blockIdx.y, n0 = blockIdx.x * TILE_N;

    float*    e12f = (float*)(smem + SM_E12);
    unsigned* adjs = (unsigned*)(smem + SM_ADJ);
    float* AiSh = (float*)(smem + SM_ROW);
    float* CiSh = AiSh + TILE_N;
    float* RvSh = CiSh + TILE_N;

    // stage e12 (16KB) and adj bitmask (16KB)
    {
        const uint4* s = (const uint4*)(g_e12 + b*NN);
        uint4* d = (uint4*)e12f;
#pragma unroll
        for (int k = 0; k < 4; k++) d[tid + k*256] = s[tid + k*256];
    }
    {
        const uint4* s = (const uint4*)(g_adj + (size_t)n0*64);
        uint4* d = (uint4*)adjs;
#pragma unroll
        for (int k = 0; k < 4; k++) d[tid + k*256] = s[tid + k*256];
    }
    if (tid < TILE_N) {
        AiSh[tid] = g_eA[b*NN + n0 + tid];
        CiSh[tid] = g_eC[b*NN + n0 + tid];
    }
    __syncthreads();

    // ---- denominators (8 rows per warp) ----
#pragma unroll 1
    for (int k = 0; k < 8; k++) {
        int r = wid*8 + k;
        float Ai = AiSh[r], Ci = CiSh[r];
        const unsigned* arow = adjs + r*64;
        float sum = 0.f;
#pragma unroll 4
        for (int i2 = 0; i2 < 32; i2++) {
            float4 ev = *(const float4*)(e12f + i2*128 + lane*4);
            unsigned bits = arow[i2*2 + (lane >> 4)];
            unsigned bp = (lane & 15) * 2;
            float nu0 = fmaxf(Ai*ev.x, Ci*ev.y);
            float nu1 = fmaxf(Ai*ev.z, Ci*ev.w);
            sum += ((bits >> bp) & 1u) ? nu0 : 0.f;
            sum += ((bits >> (bp+1)) & 1u) ? nu1 : 0.f;
        }
#pragma unroll
        for (int o = 16; o; o >>= 1) sum += __shfl_xor_sync(0xffffffffu, sum, o);
        if (lane == 0) RvSh[r] = 1.f / sum;
    }
    __syncthreads();

    // coalesced alpha mapping
    int q = lane & 15, half = lane >> 4;

    // B staging: row = tid>>1, 4 uint4 per thread (half-row (tid&1)*4..+3)
    int brow = tid >> 1, bh = (tid & 1) * 4;
    const uint4* grow = (const uint4*)(g_hT + ((size_t)(b*128 + brow)) * NN);
    unsigned b_xor_st = (unsigned)((brow & 7) << 4);
    unsigned bst_row = (unsigned)(brow * 128);

    // warp GEMM tiling: warp -> n-half 32, d-quarter 32
    int n0w = (wid >> 2) * 32, d0w = (wid & 3) * 32;
    int arow_l = lane & 15;
    unsigned acol_l = (lane >> 4) * 16;
    int brow_l = (lane & 7) + ((lane >> 4) << 3);
    unsigned bcol_l = ((lane >> 3) & 1) * 16;
    unsigned a_xor = (unsigned)((arow_l & 7) << 4);
    unsigned b_xor = (unsigned)((brow_l & 7) << 4);
    uint32_t a_row_base = sb + SM_A + (unsigned)((n0w + arow_l) * 128);
    uint32_t b_row_base = sb + SM_B + (unsigned)((d0w + brow_l) * 128);

    float acc[2][4][4];
#pragma unroll
    for (int i = 0; i < 2; i++)
#pragma unroll
        for (int j = 0; j < 4; j++)
#pragma unroll
            for (int k = 0; k < 4; k++) acc[i][j][k] = 0.f;

    // producer alpha lambda (chunk cc -> A buffer abuf)
    auto alpha_phase = [&](int cc, unsigned abuf) {
        int m0 = cc * KCHUNK;
#pragma unroll
        for (int i = 0; i < 4; i++) {
            int rr = wid*8 + i*2 + half;
            float Ai = AiSh[rr], Ci = CiSh[rr], Rv = RvSh[rr];
            int mloc = q*4;
            int m = m0 + mloc;
            float4 e01 = *(const float4*)(e12f + 2*m);
            float4 e23 = *(const float4*)(e12f + 2*m + 4);
            float n0v = fmaxf(Ai*e01.x, Ci*e01.y);
            float n1v = fmaxf(Ai*e01.z, Ci*e01.w);
            float n2v = fmaxf(Ai*e23.x, Ci*e23.y);
            float n3v = fmaxf(Ai*e23.z, Ci*e23.w);
            unsigned bits = adjs[rr*64 + cc*2 + (q >> 3)];
            unsigned bp = (unsigned)((q & 7) * 4);
            float a0 = ((bits >> (bp+0)) & 1u) ? n0v*Rv : 0.f;
            float a1 = ((bits >> (bp+1)) & 1u) ? n1v*Rv : 0.f;
            float a2 = ((bits >> (bp+2)) & 1u) ? n2v*Rv : 0.f;
            float a3 = ((bits >> (bp+3)) & 1u) ? n3v*Rv : 0.f;
            __stwt((float4*)(alpha + ((size_t)(b*NN + n0 + rr))*NN + m),
                   make_float4(a0, a1, a2, a3));
            __half2 pa = __floats2half2_rn(a0, a1);
            __half2 pb = __floats2half2_rn(a2, a3);
            unsigned so = SW128((unsigned)(rr*128 + mloc*2));
            *(uint2*)(smem + SM_A + abuf + so) =
                make_uint2(*(unsigned*)&pa, *(unsigned*)&pb);
        }
    };

    // ---- prologue: B(0) + A(0), prefetch B(1) ----
    uint4 v[4];
#pragma unroll
    for (int i = 0; i < 4; i++) v[i] = grow[bh + i];
#pragma unroll
    for (int i = 0; i < 4; i++)
        *(uint4*)(smem + SM_B + bst_row + (((unsigned)(bh + i)*16u) ^ b_xor_st)) = v[i];
#pragma unroll
    for (int i = 0; i < 4; i++) v[i] = grow[8 + bh + i];
    alpha_phase(0, 0u);
    __syncthreads();

    for (int c = 0; c < NCHUNKS; c++) {
        unsigned abuf = (unsigned)(c & 1) * 8192u;
        unsigned bbuf = (unsigned)(c & 1) * 16384u;
        // MMA(c): 4 k-steps
#pragma unroll
        for (int ks = 0; ks < 4; ks++) {
            unsigned acol = (acol_l + ks*32) ^ a_xor;
            unsigned bcol = (bcol_l + ks*32) ^ b_xor;
            uint32_t af[2][4], bf[2][4];
#pragma unroll
            for (int ng = 0; ng < 2; ng++)
                ldsm4(af[ng], a_row_base + abuf + ng*2048 + acol);
#pragma unroll
            for (int dg = 0; dg < 2; dg++)
                ldsm4(bf[dg], b_row_base + bbuf + dg*2048 + bcol);
#pragma unroll
            for (int ng = 0; ng < 2; ng++)
#pragma unroll
                for (int dg = 0; dg < 2; dg++) {
                    mma_f16(acc[ng][dg*2+0], af[ng], bf[dg][0], bf[dg][1]);
                    mma_f16(acc[ng][dg*2+1], af[ng], bf[dg][2], bf[dg][3]);
                }
        }
        if (c + 1 < NCHUNKS) {
            // STS B(c+1) into other buffer, then prefetch B(c+2)
#pragma unroll
            for (int i = 0; i < 4; i++)
                *(uint4*)(smem + SM_B + (bbuf ^ 16384u) + bst_row +
                          (((unsigned)(bh + i)*16u) ^ b_xor_st)) = v[i];
            if (c + 2 < NCHUNKS) {
                size_t mo = (size_t)((c + 2) * 8);
#pragma unroll
                for (int i = 0; i < 4; i++) v[i] = grow[mo + bh + i];
            }
            // alpha(c+1) into other A buffer
            alpha_phase(c + 1, abuf ^ 8192u);
        }
        __syncthreads();
    }

    // epilogue: write out tile
#pragma unroll
    for (int ng = 0; ng < 2; ng++) {
#pragma unroll
        for (int dt = 0; dt < 4; dt++) {
            int r = n0 + n0w + ng*16 + (lane >> 2);
            int col = d0w + dt*8 + (lane & 3)*2;
            float* p = out + ((size_t)(b*NN + r))*DD + col;
            *(float2*)p = make_float2(acc[ng][dt][0], acc[ng][dt][1]);
            *(float2*)(p + 8*DD) = make_float2(acc[ng][dt][2], acc[ng][dt][3]);
        }
    }
}

// ---------------- launch ----------------
extern "C" void kernel_launch(void* const* d_in, const int* in_sizes, int n_in,
                              void* d_out, int out_size) {
    const float* x    = (const float*)d_in[0];
    const int*   adj  = (const int*)  d_in[1];
    const float* W    = (const float*)d_in[2];
    const float* avec = (const float*)d_in[3];
    float* out   = (float*)d_out;
    float* alpha = out + (size_t)BN*DD;

    cudaFuncSetAttribute(k_main, cudaFuncAttributeMaxDynamicSharedMemorySize,
                         SM_TOTAL);

    k_pack<<<1024, 256>>>(adj);
    k_h<<<BN/32, 128>>>(x, W, avec);
    dim3 grid(NN/TILE_N, BB);
    k_main<<<grid, 256, SM_TOTAL>>>(out, alpha);
}